// round 1
// baseline (speedup 1.0000x reference)
#include <cuda_runtime.h>

#define NN 100000
#define EE 800000
#define HH 128
#define BB 64

// ---------------- scratch (device globals: no runtime allocation) ----------------
__device__ float g_u[(size_t)NN * HH];      // node features per hop
__device__ float g_mean[(size_t)NN * HH];   // seg_mean(ea*u[col]) per node
__device__ float g_third[NN];               // seg_mean(ee) per node (per hop)
__device__ int   g_deg[NN];
__device__ int   g_start[NN + 1];
__device__ int   g_cursor[NN];
__device__ int   g_ccol[EE];
__device__ float g_cea[EE];
__device__ float g_gs0[BB * HH], g_gs1[BB * HH];
__device__ float g_cnt[2 * BB];
__device__ float g_v0t[BB * HH], g_v1t[BB * HH];
__device__ float g_scal[BB * 10];           // s0,s1,p0,p1,a0,a1,d00,d01,d10,d11
__device__ float g_spvec[HH], g_actop[HH], g_acbot[HH];
__device__ float g_c0;

// ---------------- small utility kernels ----------------
__global__ void k_zero() {
    int i = blockIdx.x * blockDim.x + threadIdx.x;
    if (i < NN) { g_deg[i] = 0; g_cursor[i] = 0; }
    if (i < BB * HH) { g_gs0[i] = 0.f; g_gs1[i] = 0.f; }
    if (i < 2 * BB) { g_cnt[i] = 0.f; }
}

// precompute folded final-layer vectors:
// sp_vec[h]  = sum_j sp_w[h,j]   * last_w[j]
// ac_top[k]  = sum_j ac_w[k,j]   * last_w[H+j]   (k <  H)
// ac_bot[k]  = sum_j ac_w[H+k,j] * last_w[H+j]
// c0 = sp_b . last_w[:H] + ac_b . last_w[H:] + last_b
__global__ void k_prevec(const float* __restrict__ spw, const float* __restrict__ spb,
                         const float* __restrict__ acw, const float* __restrict__ acb,
                         const float* __restrict__ lastw, const float* __restrict__ lastb) {
    int t = threadIdx.x;  // 256
    if (t < HH) {
        float s = 0.f;
        for (int j = 0; j < HH; j++) s += spw[t * HH + j] * lastw[j];
        g_spvec[t] = s;
    }
    {
        float s = 0.f;
        for (int j = 0; j < HH; j++) s += acw[t * HH + j] * lastw[HH + j];
        if (t < HH) g_actop[t] = s; else g_acbot[t - HH] = s;
    }
    if (t < 32) {
        float s = 0.f;
        for (int j = t; j < HH; j += 32) s += spb[j] * lastw[j] + acb[j] * lastw[HH + j];
        for (int o = 16; o; o >>= 1) s += __shfl_down_sync(0xffffffffu, s, o);
        if (t == 0) g_c0 = s + lastb[0];
    }
}

__global__ void k_hist(const int* __restrict__ row) {
    int e = blockIdx.x * blockDim.x + threadIdx.x;
    if (e < EE) atomicAdd(&g_deg[row[e]], 1);
}

__global__ void k_scan() {
    __shared__ int ss[1024];
    int t = threadIdx.x;
    const int chunk = (NN + 1023) / 1024;
    int lo = t * chunk;
    int hi = lo + chunk; if (hi > NN) hi = NN;
    int s = 0;
    for (int i = lo; i < hi; i++) s += g_deg[i];
    ss[t] = s;
    __syncthreads();
    for (int off = 1; off < 1024; off <<= 1) {
        int v = (t >= off) ? ss[t - off] : 0;
        __syncthreads();
        ss[t] += v;
        __syncthreads();
    }
    int run = ss[t] - s;  // exclusive prefix for this chunk
    for (int i = lo; i < hi; i++) { g_start[i] = run; run += g_deg[i]; }
    if (t == 1023) g_start[NN] = run;
}

__global__ void k_fill(const int* __restrict__ row, const int* __restrict__ col,
                       const float* __restrict__ ea) {
    int e = blockIdx.x * blockDim.x + threadIdx.x;
    if (e >= EE) return;
    int r = row[e];
    int p = atomicAdd(&g_cursor[r], 1);
    int idx = g_start[r] + p;
    g_ccol[idx] = col[e];
    g_cea[idx]  = ea[e];
}

// hop-0 third term only (u == 0 so no gather needed)
__global__ void k_third0(const float* __restrict__ l3w, const float* __restrict__ l3b) {
    int n = blockIdx.x * blockDim.x + threadIdx.x;
    if (n >= NN) return;
    float w = l3w[0], b = l3b[0];
    int s = g_start[n], e = g_start[n + 1];
    float acc = 0.f;
    for (int t = s; t < e; t++) acc += fmaxf(g_cea[t] * w + b, 0.f);
    g_third[n] = (e > s) ? acc / (float)(e - s) : 0.f;
}

// hop-0 node update: u = relu(x*l0w + third*l2w + (l0b+l1b+l2b))
__global__ void k_node0(const float* __restrict__ x,
                        const float* __restrict__ l0w, const float* __restrict__ l0b,
                        const float* __restrict__ l1b,
                        const float* __restrict__ l2w, const float* __restrict__ l2b) {
    int i = blockIdx.x * blockDim.x + threadIdx.x;
    if (i >= NN * HH) return;
    int n = i >> 7, h = i & 127;
    float v = x[n] * l0w[h] + g_third[n] * l2w[h] + l0b[h] + l1b[h] + l2b[h];
    g_u[i] = fmaxf(v, 0.f);
}

// edge aggregation (hops 1..): warp per node, CSR gather, no atomics.
__global__ void k_gather(const float* __restrict__ l3w, const float* __restrict__ l3b) {
    int warp = threadIdx.x >> 5, lane = threadIdx.x & 31;
    int n = blockIdx.x * 8 + warp;
    if (n >= NN) return;
    float w = l3w[0], b = l3b[0];
    int s = g_start[n], e = g_start[n + 1];
    float ax = 0.f, ay = 0.f, az = 0.f, aw = 0.f, tacc = 0.f;
    for (int t = s; t < e; t++) {
        int c = g_ccol[t];
        float a = g_cea[t];
        float4 v = *reinterpret_cast<const float4*>(&g_u[(size_t)c * HH + lane * 4]);
        ax += a * v.x; ay += a * v.y; az += a * v.z; aw += a * v.w;
        tacc += fmaxf(a * w + b, 0.f);
    }
    float inv = (e > s) ? 1.f / (float)(e - s) : 0.f;
    float4 out = make_float4(ax * inv, ay * inv, az * inv, aw * inv);
    *reinterpret_cast<float4*>(&g_mean[(size_t)n * HH + lane * 4]) = out;
    if (lane == 0) g_third[n] = tacc * inv;
}

// node matmul + fused hop update: u = relu(x*l0w + mean@W1 + third*l2w + biases)
// block: 128 threads (one output column each), 32 nodes per block, W1 + A-tile in smem.
__global__ __launch_bounds__(128) void k_mm(
    const float* __restrict__ x, const float* __restrict__ W1,
    const float* __restrict__ l0w, const float* __restrict__ l2w,
    const float* __restrict__ b0, const float* __restrict__ b1,
    const float* __restrict__ b2) {
    extern __shared__ float sm[];
    float* sW = sm;                                  // 128*128
    float (*sA)[HH] = (float(*)[HH])(sm + HH * HH);  // 32*128
    int h = threadIdx.x;
    for (int i = h; i < HH * HH; i += HH) sW[i] = W1[i];
    int n0 = blockIdx.x * 32;
    for (int j = 0; j < 32; j++) sA[j][h] = g_mean[(size_t)(n0 + j) * HH + h];
    __syncthreads();
    float bias = b0[h] + b1[h] + b2[h];
    float w0 = l0w[h], w2 = l2w[h];
    for (int j0 = 0; j0 < 32; j0 += 4) {
        float a0 = 0.f, a1 = 0.f, a2 = 0.f, a3 = 0.f;
        #pragma unroll 16
        for (int k = 0; k < HH; k++) {
            float w = sW[k * HH + h];
            a0 += sA[j0 + 0][k] * w;
            a1 += sA[j0 + 1][k] * w;
            a2 += sA[j0 + 2][k] * w;
            a3 += sA[j0 + 3][k] * w;
        }
        int n = n0 + j0;
        g_u[(size_t)(n + 0) * HH + h] = fmaxf(x[n + 0] * w0 + g_third[n + 0] * w2 + bias + a0, 0.f);
        g_u[(size_t)(n + 1) * HH + h] = fmaxf(x[n + 1] * w0 + g_third[n + 1] * w2 + bias + a1, 0.f);
        g_u[(size_t)(n + 2) * HH + h] = fmaxf(x[n + 2] * w0 + g_third[n + 2] * w2 + bias + a2, 0.f);
        g_u[(size_t)(n + 3) * HH + h] = fmaxf(x[n + 3] * w0 + g_third[n + 3] * w2 + bias + a3, 0.f);
    }
}

// per-graph pooled sums (batch is sorted -> accumulate in registers, flush on change)
__global__ void k_pool(const float* __restrict__ x, const int* __restrict__ batch) {
    int h = threadIdx.x;               // 128
    int n0 = blockIdx.x * 512;
    if (n0 >= NN) return;
    int n1 = n0 + 512; if (n1 > NN) n1 = NN;
    int gcur = batch[n0];
    float a0 = 0.f, a1 = 0.f, c0 = 0.f, c1 = 0.f;
    for (int n = n0; n < n1; n++) {
        int g = batch[n];
        if (g != gcur) {
            atomicAdd(&g_gs0[gcur * HH + h], a0);
            atomicAdd(&g_gs1[gcur * HH + h], a1);
            if (h == 0) { atomicAdd(&g_cnt[gcur], c0); atomicAdd(&g_cnt[BB + gcur], c1); }
            a0 = a1 = c0 = c1 = 0.f;
            gcur = g;
        }
        float xv = x[n];
        float uv = g_u[(size_t)n * HH + h];
        a0 += uv * (1.f - xv); a1 += uv * xv;
        c0 += 1.f - xv;        c1 += xv;
    }
    atomicAdd(&g_gs0[gcur * HH + h], a0);
    atomicAdd(&g_gs1[gcur * HH + h], a1);
    if (h == 0) { atomicAdd(&g_cnt[gcur], c0); atomicAdd(&g_cnt[BB + gcur], c1); }
}

// per-graph: hc0/hc1, folded attention vectors v0/v1 = att_w @ hc, and 10 scalars
__global__ void k_graph(const float* __restrict__ attw, const float* __restrict__ attb) {
    __shared__ float hc0[HH], hc1[HH], v0[2 * HH], v1[2 * HH];
    int g = blockIdx.x, t = threadIdx.x;  // 256 threads
    if (t < HH) {
        float c0 = g_cnt[g], c1 = g_cnt[BB + g];
        hc0[t] = (c0 > 0.f) ? g_gs0[g * HH + t] / c0 : 0.f;
        hc1[t] = (c1 > 0.f) ? g_gs1[g * HH + t] / c1 : 0.f;
    }
    __syncthreads();
    {
        float s0 = 0.f, s1 = 0.f;
        const float* wrow = attw + t * HH;
        for (int j = 0; j < HH; j++) { float w = wrow[j]; s0 += w * hc0[j]; s1 += w * hc1[j]; }
        v0[t] = s0; v1[t] = s1;
        if (t < HH) { g_v0t[g * HH + t] = s0; g_v1t[g * HH + t] = s1; }
    }
    __syncthreads();
    int warp = t >> 5, lane = t & 31;
    for (int id = warp; id < 10; id += 8) {
        const float* vec; const float* hc;
        switch (id) {
            case 0: vec = attb;     hc = hc0; break;  // s0
            case 1: vec = attb;     hc = hc1; break;  // s1
            case 2: vec = g_spvec;  hc = hc0; break;  // p0
            case 3: vec = g_spvec;  hc = hc1; break;  // p1
            case 4: vec = g_acbot;  hc = hc0; break;  // a0
            case 5: vec = g_acbot;  hc = hc1; break;  // a1
            case 6: vec = v0 + HH;  hc = hc0; break;  // d00
            case 7: vec = v0 + HH;  hc = hc1; break;  // d01
            case 8: vec = v1 + HH;  hc = hc0; break;  // d10
            default: vec = v1 + HH; hc = hc1; break;  // d11
        }
        float s = 0.f;
        for (int j = lane; j < HH; j += 32) s += vec[j] * hc[j];
        for (int o = 16; o; o >>= 1) s += __shfl_down_sync(0xffffffffu, s, o);
        if (lane == 0) g_scal[g * 10 + id] = s;
    }
}

// per-node head: 3 dots of length 128 + softmax over 2 + folded output
__global__ void k_final(const float* __restrict__ x, const int* __restrict__ batch,
                        float* __restrict__ out) {
    int warp = threadIdx.x >> 5, lane = threadIdx.x & 31;
    int n = blockIdx.x * 8 + warp;
    if (n >= NN) return;
    int g = batch[n];
    float4 uv = *reinterpret_cast<const float4*>(&g_u[(size_t)n * HH + lane * 4]);
    float4 vA = *reinterpret_cast<const float4*>(&g_v0t[g * HH + lane * 4]);
    float4 vB = *reinterpret_cast<const float4*>(&g_v1t[g * HH + lane * 4]);
    float4 vC = *reinterpret_cast<const float4*>(&g_actop[lane * 4]);
    float da = uv.x * vA.x + uv.y * vA.y + uv.z * vA.z + uv.w * vA.w;
    float db = uv.x * vB.x + uv.y * vB.y + uv.z * vB.z + uv.w * vB.w;
    float dc = uv.x * vC.x + uv.y * vC.y + uv.z * vC.z + uv.w * vC.w;
    for (int o = 16; o; o >>= 1) {
        da += __shfl_down_sync(0xffffffffu, da, o);
        db += __shfl_down_sync(0xffffffffu, db, o);
        dc += __shfl_down_sync(0xffffffffu, dc, o);
    }
    if (lane == 0) {
        const float* sc = &g_scal[g * 10];
        bool xb = x[n] > 0.5f;
        float w0 = da + (xb ? sc[6] : sc[7]) + sc[0];
        float w1 = db + (xb ? sc[8] : sc[9]) + sc[1];
        float m = fmaxf(w0, w1);
        float e0 = __expf(w0 - m), e1 = __expf(w1 - m);
        float sw = e0 / (e0 + e1);
        out[n] = sw * sc[2] + (1.f - sw) * sc[3] + dc + (xb ? sc[4] : sc[5]) + g_c0;
    }
}

// ---------------- launch ----------------
extern "C" void kernel_launch(void* const* d_in, const int* in_sizes, int n_in,
                              void* d_out, int out_size) {
    // inputs: x, edge_index, edge_attr, batch, [num_graphs], l0_w, l0_b, l1_w, l1_b,
    //         l2_w, l2_b, l3_w, l3_b, att_w, att_b, sp_w, sp_b, ac_w, ac_b, last_w, last_b
    int base = (n_in >= 21) ? 5 : 4;
    const float* x     = (const float*)d_in[0];
    const int*   ei    = (const int*)d_in[1];
    const float* ea    = (const float*)d_in[2];
    const int*   batch = (const int*)d_in[3];
    const float* l0w   = (const float*)d_in[base + 0];
    const float* l0b   = (const float*)d_in[base + 1];
    const float* l1w   = (const float*)d_in[base + 2];
    const float* l1b   = (const float*)d_in[base + 3];
    const float* l2w   = (const float*)d_in[base + 4];
    const float* l2b   = (const float*)d_in[base + 5];
    const float* l3w   = (const float*)d_in[base + 6];
    const float* l3b   = (const float*)d_in[base + 7];
    const float* attw  = (const float*)d_in[base + 8];
    const float* attb  = (const float*)d_in[base + 9];
    const float* spw   = (const float*)d_in[base + 10];
    const float* spb   = (const float*)d_in[base + 11];
    const float* acw   = (const float*)d_in[base + 12];
    const float* acb   = (const float*)d_in[base + 13];
    const float* lastw = (const float*)d_in[base + 14];
    const float* lastb = (const float*)d_in[base + 15];
    const int* row = ei;
    const int* col = ei + EE;
    float* out = (float*)d_out;

    const int SMEM_MM = (HH * HH + 32 * HH) * (int)sizeof(float);  // 81920 B
    cudaFuncSetAttribute(k_mm, cudaFuncAttributeMaxDynamicSharedMemorySize, SMEM_MM);

    k_zero<<<(NN + 255) / 256, 256>>>();
    k_prevec<<<1, 256>>>(spw, spb, acw, acb, lastw, lastb);
    k_hist<<<(EE + 255) / 256, 256>>>(row);
    k_scan<<<1, 1024>>>();
    k_fill<<<(EE + 255) / 256, 256>>>(row, col, ea);

    // hop 0 (u == 0: skip gather and matmul)
    k_third0<<<(NN + 255) / 256, 256>>>(l3w + 0, l3b + 0);
    k_node0<<<(NN * HH + 255) / 256, 256>>>(x, l0w, l0b, l1b, l2w, l2b);

    // hops 1, 2
    for (int i = 1; i < 3; i++) {
        k_gather<<<(NN + 7) / 8, 256>>>(l3w + i, l3b + i);
        k_mm<<<NN / 32, 128, SMEM_MM>>>(x, l1w + i * HH * HH,
                                        l0w + i * HH, l2w + i * HH,
                                        l0b + i * HH, l1b + i * HH, l2b + i * HH);
    }

    k_pool<<<(NN + 511) / 512, 128>>>(x, batch);
    k_graph<<<BB, 256>>>(attw, attb);
    k_final<<<NN / 8, 256>>>(x, batch, out);
}

// round 2
// speedup vs baseline: 1.6313x; 1.6313x over previous
#include <cuda_runtime.h>

#define NN 100000
#define EE 800000
#define HH 128
#define BB 64
#define NB1 196   // ceil(NN/512)

// ---------------- scratch (device globals: no runtime allocation) ----------------
__device__ float g_u[(size_t)NN * HH];      // node features per hop
__device__ float g_mean[(size_t)NN * HH];   // seg_mean(ea*u[col]) per node
__device__ float g_third[NN];               // seg_mean(ee) per node (per hop)
__device__ int   g_deg[NN];
__device__ int   g_start[NN + 1];
__device__ int   g_cursor[NN];
__device__ int   g_bsum[NB1 + 4];
__device__ int   g_boff[NB1 + 4];
__device__ int   g_ccol[EE];
__device__ float g_cea[EE];
__device__ float g_gs0[BB * HH], g_gs1[BB * HH];
__device__ float g_cnt[2 * BB];
__device__ float g_v0t[BB * HH], g_v1t[BB * HH];
__device__ float g_scal[BB * 10];           // s0,s1,p0,p1,a0,a1,d00,d01,d10,d11
__device__ float g_spvec[HH], g_actop[HH], g_acbot[HH];
__device__ float g_c0;

// ---------------- small utility kernels ----------------
__global__ void k_zero() {
    int i = blockIdx.x * blockDim.x + threadIdx.x;
    if (i < NN) g_deg[i] = 0;
    if (i < BB * HH) { g_gs0[i] = 0.f; g_gs1[i] = 0.f; }
    if (i < 2 * BB) { g_cnt[i] = 0.f; }
}

// precompute folded final-layer vectors (see round-1 notes)
__global__ void k_prevec(const float* __restrict__ spw, const float* __restrict__ spb,
                         const float* __restrict__ acw, const float* __restrict__ acb,
                         const float* __restrict__ lastw, const float* __restrict__ lastb) {
    int t = threadIdx.x;  // 256
    if (t < HH) {
        float s = 0.f;
        for (int j = 0; j < HH; j++) s += spw[t * HH + j] * lastw[j];
        g_spvec[t] = s;
    }
    {
        float s = 0.f;
        for (int j = 0; j < HH; j++) s += acw[t * HH + j] * lastw[HH + j];
        if (t < HH) g_actop[t] = s; else g_acbot[t - HH] = s;
    }
    if (t < 32) {
        float s = 0.f;
        for (int j = t; j < HH; j += 32) s += spb[j] * lastw[j] + acb[j] * lastw[HH + j];
        for (int o = 16; o; o >>= 1) s += __shfl_down_sync(0xffffffffu, s, o);
        if (t == 0) g_c0 = s + lastb[0];
    }
}

__global__ void k_hist(const int* __restrict__ row) {
    int e = blockIdx.x * blockDim.x + threadIdx.x;
    if (e < EE) atomicAdd(&g_deg[row[e]], 1);
}

// ---- hierarchical scan: scan1 (block sums) -> scan2 (scan block sums) -> scan3 ----
__global__ void k_scan1() {
    int t = threadIdx.x;                     // 256 threads, 512 nodes/block
    int n0 = blockIdx.x * 512;
    int s = 0;
    int i = n0 + t;
    if (i < NN) s += g_deg[i];
    if (i + 256 < n0 + 512 && i + 256 < NN) s += g_deg[i + 256];
    int lane = t & 31, warp = t >> 5;
    for (int o = 16; o; o >>= 1) s += __shfl_down_sync(0xffffffffu, s, o);
    __shared__ int ws[8];
    if (lane == 0) ws[warp] = s;
    __syncthreads();
    if (t == 0) {
        int tot = 0;
        #pragma unroll
        for (int w = 0; w < 8; w++) tot += ws[w];
        g_bsum[blockIdx.x] = tot;
    }
}

__global__ void k_scan2() {
    __shared__ int sh[256];
    int t = threadIdx.x;
    int v = (t < NB1) ? g_bsum[t] : 0;
    sh[t] = v;
    __syncthreads();
    for (int off = 1; off < 256; off <<= 1) {
        int u = (t >= off) ? sh[t - off] : 0;
        __syncthreads();
        sh[t] += u;
        __syncthreads();
    }
    if (t < NB1) g_boff[t] = sh[t] - v;   // exclusive
    if (t == 0) g_start[NN] = EE;
}

__global__ void k_scan3() {
    int t = threadIdx.x, blk = blockIdx.x;   // 256 threads, 2 nodes each
    int i0 = blk * 512 + t * 2;
    int d0 = (i0 < NN) ? g_deg[i0] : 0;
    int d1 = (i0 + 1 < NN) ? g_deg[i0 + 1] : 0;
    int s = d0 + d1;
    int lane = t & 31, warp = t >> 5;
    int v = s;
    for (int o = 1; o < 32; o <<= 1) {
        int u = __shfl_up_sync(0xffffffffu, v, o);
        if (lane >= o) v += u;
    }
    __shared__ int ws[8], wo[8];
    if (lane == 31) ws[warp] = v;
    __syncthreads();
    if (t == 0) {
        int run = 0;
        #pragma unroll
        for (int w = 0; w < 8; w++) { wo[w] = run; run += ws[w]; }
    }
    __syncthreads();
    int ex = v - s + wo[warp] + g_boff[blk];
    if (i0 < NN)     { g_start[i0] = ex;          g_cursor[i0] = ex; }
    if (i0 + 1 < NN) { g_start[i0 + 1] = ex + d0; g_cursor[i0 + 1] = ex + d0; }
}

__global__ void k_fill(const int* __restrict__ row, const int* __restrict__ col,
                       const float* __restrict__ ea) {
    int e = blockIdx.x * blockDim.x + threadIdx.x;
    if (e >= EE) return;
    int r = row[e];
    int idx = atomicAdd(&g_cursor[r], 1);
    g_ccol[idx] = col[e];
    g_cea[idx]  = ea[e];
}

// hop-0 third term only (u == 0 so no gather needed)
__global__ void k_third0(const float* __restrict__ l3w, const float* __restrict__ l3b) {
    int n = blockIdx.x * blockDim.x + threadIdx.x;
    if (n >= NN) return;
    float w = l3w[0], b = l3b[0];
    int s = g_start[n], e = g_start[n + 1];
    float acc = 0.f;
    for (int t = s; t < e; t++) acc += fmaxf(g_cea[t] * w + b, 0.f);
    g_third[n] = (e > s) ? acc / (float)(e - s) : 0.f;
}

// hop-0 node update: u = relu(x*l0w + third*l2w + (l0b+l1b+l2b))
__global__ void k_node0(const float* __restrict__ x,
                        const float* __restrict__ l0w, const float* __restrict__ l0b,
                        const float* __restrict__ l1b,
                        const float* __restrict__ l2w, const float* __restrict__ l2b) {
    int i = blockIdx.x * blockDim.x + threadIdx.x;
    if (i >= NN * HH) return;
    int n = i >> 7, h = i & 127;
    float v = x[n] * l0w[h] + g_third[n] * l2w[h] + l0b[h] + l1b[h] + l2b[h];
    g_u[i] = fmaxf(v, 0.f);
}

// edge aggregation (hops 1..): warp per node, CSR gather, no atomics, 2-edge unroll.
__global__ void k_gather(const float* __restrict__ l3w, const float* __restrict__ l3b) {
    int warp = threadIdx.x >> 5, lane = threadIdx.x & 31;
    int n = blockIdx.x * 8 + warp;
    if (n >= NN) return;
    float w = l3w[0], b = l3b[0];
    int s = g_start[n], e = g_start[n + 1];
    float ax = 0.f, ay = 0.f, az = 0.f, aw = 0.f, tacc = 0.f;
    int t = s;
    for (; t + 1 < e; t += 2) {
        int c0 = g_ccol[t], c1 = g_ccol[t + 1];
        float a0 = g_cea[t], a1 = g_cea[t + 1];
        float4 v0 = *reinterpret_cast<const float4*>(&g_u[(size_t)c0 * HH + lane * 4]);
        float4 v1 = *reinterpret_cast<const float4*>(&g_u[(size_t)c1 * HH + lane * 4]);
        ax += a0 * v0.x + a1 * v1.x;
        ay += a0 * v0.y + a1 * v1.y;
        az += a0 * v0.z + a1 * v1.z;
        aw += a0 * v0.w + a1 * v1.w;
        tacc += fmaxf(a0 * w + b, 0.f) + fmaxf(a1 * w + b, 0.f);
    }
    if (t < e) {
        int c0 = g_ccol[t];
        float a0 = g_cea[t];
        float4 v0 = *reinterpret_cast<const float4*>(&g_u[(size_t)c0 * HH + lane * 4]);
        ax += a0 * v0.x; ay += a0 * v0.y; az += a0 * v0.z; aw += a0 * v0.w;
        tacc += fmaxf(a0 * w + b, 0.f);
    }
    float inv = (e > s) ? 1.f / (float)(e - s) : 0.f;
    float4 out = make_float4(ax * inv, ay * inv, az * inv, aw * inv);
    *reinterpret_cast<float4*>(&g_mean[(size_t)n * HH + lane * 4]) = out;
    if (lane == 0) g_third[n] = tacc * inv;
}

// node matmul + fused hop update, register-tiled 4x4.
// block: 256 threads, 32 nodes, full W (128x128) + A^T (128x36) in smem.
__global__ __launch_bounds__(256) void k_mm(
    const float* __restrict__ x, const float* __restrict__ W1,
    const float* __restrict__ l0w, const float* __restrict__ l2w,
    const float* __restrict__ b0, const float* __restrict__ b1,
    const float* __restrict__ b2) {
    extern __shared__ float sm[];
    float* sW  = sm;            // [128][128] row = k
    float* sAT = sm + HH * HH;  // [128][36]  row = k (transposed A, padded)
    int tid = threadIdx.x;
    int tx = tid & 31, ty = tid >> 5;

    const float4* W4 = reinterpret_cast<const float4*>(W1);
    float4* sW4 = reinterpret_cast<float4*>(sW);
    #pragma unroll
    for (int i = tid; i < HH * HH / 4; i += 256) sW4[i] = W4[i];

    int n0 = blockIdx.x * 32;
    #pragma unroll
    for (int i = tid; i < 32 * HH; i += 256) {
        int j = i >> 7, h = i & 127;
        sAT[h * 36 + j] = g_mean[(size_t)(n0 + j) * HH + h];
    }
    __syncthreads();

    int c0 = tx * 4, j0 = ty * 4;
    float acc[4][4];
    #pragma unroll
    for (int i = 0; i < 4; i++)
        #pragma unroll
        for (int c = 0; c < 4; c++) acc[i][c] = 0.f;

    #pragma unroll 8
    for (int k = 0; k < HH; k++) {
        float4 a = *reinterpret_cast<const float4*>(&sAT[k * 36 + j0]);
        float4 w = *reinterpret_cast<const float4*>(&sW[k * HH + c0]);
        acc[0][0] += a.x * w.x; acc[0][1] += a.x * w.y; acc[0][2] += a.x * w.z; acc[0][3] += a.x * w.w;
        acc[1][0] += a.y * w.x; acc[1][1] += a.y * w.y; acc[1][2] += a.y * w.z; acc[1][3] += a.y * w.w;
        acc[2][0] += a.z * w.x; acc[2][1] += a.z * w.y; acc[2][2] += a.z * w.z; acc[2][3] += a.z * w.w;
        acc[3][0] += a.w * w.x; acc[3][1] += a.w * w.y; acc[3][2] += a.w * w.z; acc[3][3] += a.w * w.w;
    }

    float4 w0v = *reinterpret_cast<const float4*>(&l0w[c0]);
    float4 w2v = *reinterpret_cast<const float4*>(&l2w[c0]);
    float4 bb0 = *reinterpret_cast<const float4*>(&b0[c0]);
    float4 bb1 = *reinterpret_cast<const float4*>(&b1[c0]);
    float4 bb2 = *reinterpret_cast<const float4*>(&b2[c0]);
    float biasx = bb0.x + bb1.x + bb2.x, biasy = bb0.y + bb1.y + bb2.y;
    float biasz = bb0.z + bb1.z + bb2.z, biasw = bb0.w + bb1.w + bb2.w;
    #pragma unroll
    for (int i = 0; i < 4; i++) {
        int n = n0 + j0 + i;
        float xv = x[n], tv = g_third[n];
        float4 o;
        o.x = fmaxf(xv * w0v.x + tv * w2v.x + biasx + acc[i][0], 0.f);
        o.y = fmaxf(xv * w0v.y + tv * w2v.y + biasy + acc[i][1], 0.f);
        o.z = fmaxf(xv * w0v.z + tv * w2v.z + biasz + acc[i][2], 0.f);
        o.w = fmaxf(xv * w0v.w + tv * w2v.w + biasw + acc[i][3], 0.f);
        *reinterpret_cast<float4*>(&g_u[(size_t)n * HH + c0]) = o;
    }
}

// per-graph pooled sums (batch is sorted -> accumulate in registers, flush on change)
__global__ void k_pool(const float* __restrict__ x, const int* __restrict__ batch) {
    int h = threadIdx.x;               // 128
    int n0 = blockIdx.x * 512;
    if (n0 >= NN) return;
    int n1 = n0 + 512; if (n1 > NN) n1 = NN;
    int gcur = batch[n0];
    float a0 = 0.f, a1 = 0.f, c0 = 0.f, c1 = 0.f;
    for (int n = n0; n < n1; n++) {
        int g = batch[n];
        if (g != gcur) {
            atomicAdd(&g_gs0[gcur * HH + h], a0);
            atomicAdd(&g_gs1[gcur * HH + h], a1);
            if (h == 0) { atomicAdd(&g_cnt[gcur], c0); atomicAdd(&g_cnt[BB + gcur], c1); }
            a0 = a1 = c0 = c1 = 0.f;
            gcur = g;
        }
        float xv = x[n];
        float uv = g_u[(size_t)n * HH + h];
        a0 += uv * (1.f - xv); a1 += uv * xv;
        c0 += 1.f - xv;        c1 += xv;
    }
    atomicAdd(&g_gs0[gcur * HH + h], a0);
    atomicAdd(&g_gs1[gcur * HH + h], a1);
    if (h == 0) { atomicAdd(&g_cnt[gcur], c0); atomicAdd(&g_cnt[BB + gcur], c1); }
}

// per-graph: hc0/hc1, folded attention vectors v0/v1 = att_w @ hc, and 10 scalars
__global__ void k_graph(const float* __restrict__ attw, const float* __restrict__ attb) {
    __shared__ float hc0[HH], hc1[HH], v0[2 * HH], v1[2 * HH];
    int g = blockIdx.x, t = threadIdx.x;  // 256 threads
    if (t < HH) {
        float c0 = g_cnt[g], c1 = g_cnt[BB + g];
        hc0[t] = (c0 > 0.f) ? g_gs0[g * HH + t] / c0 : 0.f;
        hc1[t] = (c1 > 0.f) ? g_gs1[g * HH + t] / c1 : 0.f;
    }
    __syncthreads();
    {
        float s0 = 0.f, s1 = 0.f;
        const float* wrow = attw + t * HH;
        for (int j = 0; j < HH; j++) { float w = wrow[j]; s0 += w * hc0[j]; s1 += w * hc1[j]; }
        v0[t] = s0; v1[t] = s1;
        if (t < HH) { g_v0t[g * HH + t] = s0; g_v1t[g * HH + t] = s1; }
    }
    __syncthreads();
    int warp = t >> 5, lane = t & 31;
    for (int id = warp; id < 10; id += 8) {
        const float* vec; const float* hc;
        switch (id) {
            case 0: vec = attb;     hc = hc0; break;  // s0
            case 1: vec = attb;     hc = hc1; break;  // s1
            case 2: vec = g_spvec;  hc = hc0; break;  // p0
            case 3: vec = g_spvec;  hc = hc1; break;  // p1
            case 4: vec = g_acbot;  hc = hc0; break;  // a0
            case 5: vec = g_acbot;  hc = hc1; break;  // a1
            case 6: vec = v0 + HH;  hc = hc0; break;  // d00
            case 7: vec = v0 + HH;  hc = hc1; break;  // d01
            case 8: vec = v1 + HH;  hc = hc0; break;  // d10
            default: vec = v1 + HH; hc = hc1; break;  // d11
        }
        float s = 0.f;
        for (int j = lane; j < HH; j += 32) s += vec[j] * hc[j];
        for (int o = 16; o; o >>= 1) s += __shfl_down_sync(0xffffffffu, s, o);
        if (lane == 0) g_scal[g * 10 + id] = s;
    }
}

// per-node head: 3 dots of length 128 + softmax over 2 + folded output
__global__ void k_final(const float* __restrict__ x, const int* __restrict__ batch,
                        float* __restrict__ out) {
    int warp = threadIdx.x >> 5, lane = threadIdx.x & 31;
    int n = blockIdx.x * 8 + warp;
    if (n >= NN) return;
    int g = batch[n];
    float4 uv = *reinterpret_cast<const float4*>(&g_u[(size_t)n * HH + lane * 4]);
    float4 vA = *reinterpret_cast<const float4*>(&g_v0t[g * HH + lane * 4]);
    float4 vB = *reinterpret_cast<const float4*>(&g_v1t[g * HH + lane * 4]);
    float4 vC = *reinterpret_cast<const float4*>(&g_actop[lane * 4]);
    float da = uv.x * vA.x + uv.y * vA.y + uv.z * vA.z + uv.w * vA.w;
    float db = uv.x * vB.x + uv.y * vB.y + uv.z * vB.z + uv.w * vB.w;
    float dc = uv.x * vC.x + uv.y * vC.y + uv.z * vC.z + uv.w * vC.w;
    for (int o = 16; o; o >>= 1) {
        da += __shfl_down_sync(0xffffffffu, da, o);
        db += __shfl_down_sync(0xffffffffu, db, o);
        dc += __shfl_down_sync(0xffffffffu, dc, o);
    }
    if (lane == 0) {
        const float* sc = &g_scal[g * 10];
        bool xb = x[n] > 0.5f;
        float w0 = da + (xb ? sc[6] : sc[7]) + sc[0];
        float w1 = db + (xb ? sc[8] : sc[9]) + sc[1];
        float m = fmaxf(w0, w1);
        float e0 = __expf(w0 - m), e1 = __expf(w1 - m);
        float sw = e0 / (e0 + e1);
        out[n] = sw * sc[2] + (1.f - sw) * sc[3] + dc + (xb ? sc[4] : sc[5]) + g_c0;
    }
}

// ---------------- launch ----------------
extern "C" void kernel_launch(void* const* d_in, const int* in_sizes, int n_in,
                              void* d_out, int out_size) {
    int base = (n_in >= 21) ? 5 : 4;
    const float* x     = (const float*)d_in[0];
    const int*   ei    = (const int*)d_in[1];
    const float* ea    = (const float*)d_in[2];
    const int*   batch = (const int*)d_in[3];
    const float* l0w   = (const float*)d_in[base + 0];
    const float* l0b   = (const float*)d_in[base + 1];
    const float* l1w   = (const float*)d_in[base + 2];
    const float* l1b   = (const float*)d_in[base + 3];
    const float* l2w   = (const float*)d_in[base + 4];
    const float* l2b   = (const float*)d_in[base + 5];
    const float* l3w   = (const float*)d_in[base + 6];
    const float* l3b   = (const float*)d_in[base + 7];
    const float* attw  = (const float*)d_in[base + 8];
    const float* attb  = (const float*)d_in[base + 9];
    const float* spw   = (const float*)d_in[base + 10];
    const float* spb   = (const float*)d_in[base + 11];
    const float* acw   = (const float*)d_in[base + 12];
    const float* acb   = (const float*)d_in[base + 13];
    const float* lastw = (const float*)d_in[base + 14];
    const float* lastb = (const float*)d_in[base + 15];
    const int* row = ei;
    const int* col = ei + EE;
    float* out = (float*)d_out;

    const int SMEM_MM = (HH * HH + HH * 36) * (int)sizeof(float);  // 83968 B
    cudaFuncSetAttribute(k_mm, cudaFuncAttributeMaxDynamicSharedMemorySize, SMEM_MM);

    k_zero<<<(NN + 255) / 256, 256>>>();
    k_prevec<<<1, 256>>>(spw, spb, acw, acb, lastw, lastb);
    k_hist<<<(EE + 255) / 256, 256>>>(row);
    k_scan1<<<NB1, 256>>>();
    k_scan2<<<1, 256>>>();
    k_scan3<<<NB1, 256>>>();
    k_fill<<<(EE + 255) / 256, 256>>>(row, col, ea);

    // hop 0 (u == 0: skip gather and matmul)
    k_third0<<<(NN + 255) / 256, 256>>>(l3w + 0, l3b + 0);
    k_node0<<<(NN * HH + 255) / 256, 256>>>(x, l0w, l0b, l1b, l2w, l2b);

    // hops 1, 2
    for (int i = 1; i < 3; i++) {
        k_gather<<<(NN + 7) / 8, 256>>>(l3w + i, l3b + i);
        k_mm<<<NN / 32, 256, SMEM_MM>>>(x, l1w + i * HH * HH,
                                        l0w + i * HH, l2w + i * HH,
                                        l0b + i * HH, l1b + i * HH, l2b + i * HH);
    }

    k_pool<<<(NN + 511) / 512, 128>>>(x, batch);
    k_graph<<<BB, 256>>>(attw, attb);
    k_final<<<NN / 8, 256>>>(x, batch, out);
}